// round 10
// baseline (speedup 1.0000x reference)
#include <cuda_runtime.h>
#include <cuda_bf16.h>
#include <math.h>
#include <stdint.h>

#define DM    1024
#define DFF   4096
#define NH    16
#define DH    64
#define BATCH 4
#define SEQ   2048
#define MROWS (BATCH*SEQ)   // 8192

// ---------------- scratch (no allocation allowed) ----------------
static __device__ __nv_bfloat16 g_hh [MROWS*DM],  g_hl [MROWS*DM];
static __device__ __nv_bfloat16 g_qhi[MROWS*DM],  g_qlo[MROWS*DM];
static __device__ __nv_bfloat16 g_khi[MROWS*DM],  g_klo[MROWS*DM];
static __device__ __nv_bfloat16 g_vhi[MROWS*DM],  g_vlo[MROWS*DM];
static __device__ __nv_bfloat16 g_chi[MROWS*DM],  g_clo[MROWS*DM];
static __device__ float         g_x1 [MROWS*DM];
static __device__ __nv_bfloat16 g_fhi[(size_t)MROWS*DFF], g_flo[(size_t)MROWS*DFF];
static __device__ __nv_bfloat16 g_wqh[DM*DM], g_wql[DM*DM];
static __device__ __nv_bfloat16 g_wkh[DM*DM], g_wkl[DM*DM];
static __device__ __nv_bfloat16 g_wvh[DM*DM], g_wvl[DM*DM];
static __device__ __nv_bfloat16 g_woh[DM*DM], g_wol[DM*DM];
static __device__ __nv_bfloat16 g_w1h[DM*DFF], g_w1l[DM*DFF];
static __device__ __nv_bfloat16 g_w2h[DFF*DM], g_w2l[DFF*DM];

// ================= helpers =================
__device__ __forceinline__ uint32_t smem_u32(const void* p) {
    uint32_t a;
    asm("{ .reg .u64 t; cvta.to.shared.u64 t, %1; cvt.u32.u64 %0, t; }" : "=r"(a) : "l"(p));
    return a;
}
__device__ __forceinline__ void mma_bf16(float* c, const uint32_t* a, uint32_t b0, uint32_t b1) {
    asm volatile(
        "mma.sync.aligned.m16n8k16.row.col.f32.bf16.bf16.f32 "
        "{%0,%1,%2,%3}, {%4,%5,%6,%7}, {%8,%9}, {%0,%1,%2,%3};"
        : "+f"(c[0]), "+f"(c[1]), "+f"(c[2]), "+f"(c[3])
        : "r"(a[0]), "r"(a[1]), "r"(a[2]), "r"(a[3]), "r"(b0), "r"(b1));
}
__device__ __forceinline__ void ldmatrix_x4t(uint32_t* r, uint32_t addr) {
    asm volatile("ldmatrix.sync.aligned.m8n8.x4.trans.shared.b16 {%0,%1,%2,%3}, [%4];"
                 : "=r"(r[0]), "=r"(r[1]), "=r"(r[2]), "=r"(r[3]) : "r"(addr));
}
__device__ __forceinline__ void ldmatrix_x4(uint32_t* r, uint32_t addr) {
    asm volatile("ldmatrix.sync.aligned.m8n8.x4.shared.b16 {%0,%1,%2,%3}, [%4];"
                 : "=r"(r[0]), "=r"(r[1]), "=r"(r[2]), "=r"(r[3]) : "r"(addr));
}
__device__ __forceinline__ void cp16(uint32_t dst, const void* src) {
    asm volatile("cp.async.cg.shared.global [%0], [%1], 16;" :: "r"(dst), "l"(src));
}
#define CP_COMMIT() asm volatile("cp.async.commit_group;")
#define CP_WAIT0()  asm volatile("cp.async.wait_group 0;")
__device__ __forceinline__ uint32_t bf2_u32(__nv_bfloat162 v) { return *(uint32_t*)&v; }
__device__ __forceinline__ void split2(float a, float b, uint32_t& hi, uint32_t& lo) {
    __nv_bfloat162 h = __float22bfloat162_rn(make_float2(a, b));
    float2 hf = __bfloat1622float2(h);
    __nv_bfloat162 l = __float22bfloat162_rn(make_float2(a - hf.x, b - hf.y));
    hi = bf2_u32(h); lo = bf2_u32(l);
}

// ---------------- weight split: fp32 -> hi/lo bf16 ----------------
__global__ __launch_bounds__(256) void split_k(
    const float4* __restrict__ src, uint2* __restrict__ hi, uint2* __restrict__ lo, int n4)
{
    const int i = blockIdx.x * 256 + threadIdx.x;
    if (i >= n4) return;
    float4 v = src[i];
    uint32_t h0, l0, h1, l1;
    split2(v.x, v.y, h0, l0);
    split2(v.z, v.w, h1, l1);
    hi[i] = make_uint2(h0, h1);
    lo[i] = make_uint2(l0, l1);
}

// ---------------- LayerNorm -> hi/lo bf16 ----------------
__global__ __launch_bounds__(256) void ln_kernel(
    const float* __restrict__ x, const float* __restrict__ gamma,
    const float* __restrict__ beta,
    __nv_bfloat16* __restrict__ ohi, __nv_bfloat16* __restrict__ olo)
{
    const int row = blockIdx.x;
    const int tid = threadIdx.x;
    const float4* xr = (const float4*)(x + (size_t)row * DM);
    float4 v = xr[tid];
    float s  = v.x + v.y + v.z + v.w;
    float ss = v.x*v.x + v.y*v.y + v.z*v.z + v.w*v.w;
    #pragma unroll
    for (int off = 16; off; off >>= 1) {
        s  += __shfl_xor_sync(0xffffffffu, s,  off);
        ss += __shfl_xor_sync(0xffffffffu, ss, off);
    }
    __shared__ float sh[2][8];
    const int w = tid >> 5, lane = tid & 31;
    if (lane == 0) { sh[0][w] = s; sh[1][w] = ss; }
    __syncthreads();
    if (tid < 32) {
        s  = (lane < 8) ? sh[0][lane] : 0.f;
        ss = (lane < 8) ? sh[1][lane] : 0.f;
        #pragma unroll
        for (int off = 4; off; off >>= 1) {
            s  += __shfl_xor_sync(0xffffffffu, s,  off);
            ss += __shfl_xor_sync(0xffffffffu, ss, off);
        }
        if (lane == 0) { sh[0][0] = s; sh[1][0] = ss; }
    }
    __syncthreads();
    s = sh[0][0]; ss = sh[1][0];
    const float mean = s * (1.f/1024.f);
    const float var  = ss * (1.f/1024.f) - mean*mean;
    const float rstd = rsqrtf(var + 1e-5f);
    float4 g  = ((const float4*)gamma)[tid];
    float4 bb = ((const float4*)beta)[tid];
    float r0 = (v.x - mean) * rstd * g.x + bb.x;
    float r1 = (v.y - mean) * rstd * g.y + bb.y;
    float r2 = (v.z - mean) * rstd * g.z + bb.z;
    float r3 = (v.w - mean) * rstd * g.w + bb.w;
    uint32_t h0, l0, h1, l1;
    split2(r0, r1, h0, l0);
    split2(r2, r3, h1, l1);
    ((uint2*)(ohi + (size_t)row * DM))[tid] = make_uint2(h0, h1);
    ((uint2*)(olo + (size_t)row * DM))[tid] = make_uint2(l0, l1);
}

// ============ split-bf16 GEMM, cp.async double-buffered, 128x128 tile ============
// stage layout (bytes): A_HI [128][144] @0, A_LO @18432, B_HI [64][272] @36864, B_LO @54272
#define SA_HI 0
#define SA_LO 18432
#define SB_HI 36864
#define SB_LO 54272
#define STAGE 71680
#define SMEM_BYTES (2*STAGE)

// MODE 1: QKV -> hi/lo bf16 [B,H,T,D]; MODE 2: GELU -> hi/lo bf16;
// MODE 3: +bias+res -> fp32; MODE 4: gated blend -> fp32
template<int MODE>
__global__ void __launch_bounds__(256) mma_gemm(
    const __nv_bfloat16* __restrict__ Ahi, const __nv_bfloat16* __restrict__ Alo,
    const __nv_bfloat16* __restrict__ Bhi, const __nv_bfloat16* __restrict__ Blo,
    const float* __restrict__ bias, float* __restrict__ Cf,
    __nv_bfloat16* __restrict__ Chi, __nv_bfloat16* __restrict__ Clo,
    int M, int N, int K,
    const float* __restrict__ res, const float* __restrict__ res2,
    const float* __restrict__ gate)
{
    extern __shared__ char smem[];
    const uint32_t sb = smem_u32(smem);
    const int tid  = threadIdx.x;
    const int lane = tid & 31, wid = tid >> 5;
    const int bm = blockIdx.y * 128, bn = blockIdx.x * 128;
    const int wm = (wid & 3) * 32;
    const int wn = (wid >> 2) * 64;

    const int lr4 = lane >> 2, lc4 = lane & 3;
    const int g = lane >> 3, lr8 = lane & 7;
    const int b_krow = lr8 + (g & 1) * 8;
    const int b_ncol = (g >> 1) * 8;

    float acc[2][8][4];
    #pragma unroll
    for (int a = 0; a < 2; a++)
        #pragma unroll
        for (int b = 0; b < 8; b++)
            #pragma unroll
            for (int c = 0; c < 4; c++) acc[a][b][c] = 0.f;

    const int nchunk = K >> 6;

    // async copy of one K-chunk into stage stg
    auto copy_stage = [&](int ch, int stg) {
        const int k0 = ch << 6;
        const uint32_t s = sb + stg * STAGE;
        #pragma unroll
        for (int i = 0; i < 4; i++) {
            const int idx = i * 256 + tid;
            {   // A planes: [128 rows][8 x 16B]
                const int r = idx >> 3, c = idx & 7;
                const size_t go = ((size_t)(bm + r) * K + k0) * 2 + c * 16;
                cp16(s + SA_HI + r * 144 + c * 16, (const char*)Ahi + go);
                cp16(s + SA_LO + r * 144 + c * 16, (const char*)Alo + go);
            }
            {   // B planes: [64 rows][16 x 16B]
                const int kr = idx >> 4, c = idx & 15;
                const size_t go = ((size_t)(k0 + kr) * N + bn) * 2 + c * 16;
                cp16(s + SB_HI + kr * 272 + c * 16, (const char*)Bhi + go);
                cp16(s + SB_LO + kr * 272 + c * 16, (const char*)Blo + go);
            }
        }
    };

    copy_stage(0, 0);
    CP_COMMIT();

    for (int ch = 0; ch < nchunk; ch++) {
        CP_WAIT0();
        __syncthreads();
        if (ch + 1 < nchunk) { copy_stage(ch + 1, (ch + 1) & 1); CP_COMMIT(); }

        const char* s = smem + (ch & 1) * STAGE;
        const uint32_t su = sb + (ch & 1) * STAGE;
        #pragma unroll
        for (int ks = 0; ks < 4; ks++) {
            uint32_t ah[2][4], al[2][4];
            #pragma unroll
            for (int mt = 0; mt < 2; mt++) {
                const uint32_t r0 = (uint32_t)((wm + mt * 16 + lr4) * 144 + ks * 32 + lc4 * 4);
                ah[mt][0] = *(const uint32_t*)(s + SA_HI + r0);
                ah[mt][1] = *(const uint32_t*)(s + SA_HI + r0 + 8 * 144);
                ah[mt][2] = *(const uint32_t*)(s + SA_HI + r0 + 16);
                ah[mt][3] = *(const uint32_t*)(s + SA_HI + r0 + 8 * 144 + 16);
                al[mt][0] = *(const uint32_t*)(s + SA_LO + r0);
                al[mt][1] = *(const uint32_t*)(s + SA_LO + r0 + 8 * 144);
                al[mt][2] = *(const uint32_t*)(s + SA_LO + r0 + 16);
                al[mt][3] = *(const uint32_t*)(s + SA_LO + r0 + 8 * 144 + 16);
            }
            #pragma unroll
            for (int p = 0; p < 4; p++) {
                const uint32_t baddr = su + SB_HI
                    + (uint32_t)((ks * 16 + b_krow) * 272 + (wn + p * 16 + b_ncol) * 2);
                uint32_t bh[4], bl[4];
                ldmatrix_x4t(bh, baddr);
                ldmatrix_x4t(bl, baddr + (SB_LO - SB_HI));
                #pragma unroll
                for (int mt = 0; mt < 2; mt++) {
                    mma_bf16(acc[mt][2*p],   ah[mt], bh[0], bh[1]);
                    mma_bf16(acc[mt][2*p+1], ah[mt], bh[2], bh[3]);
                }
                #pragma unroll
                for (int mt = 0; mt < 2; mt++) {
                    mma_bf16(acc[mt][2*p],   ah[mt], bl[0], bl[1]);
                    mma_bf16(acc[mt][2*p+1], ah[mt], bl[2], bl[3]);
                }
                #pragma unroll
                for (int mt = 0; mt < 2; mt++) {
                    mma_bf16(acc[mt][2*p],   al[mt], bh[0], bh[1]);
                    mma_bf16(acc[mt][2*p+1], al[mt], bh[2], bh[3]);
                }
            }
        }
        __syncthreads();
    }

    // ---- epilogue ----
    #pragma unroll
    for (int mt = 0; mt < 2; mt++) {
        #pragma unroll
        for (int half = 0; half < 2; half++) {
            const int m = bm + wm + mt * 16 + half * 8 + lr4;
            #pragma unroll
            for (int nt = 0; nt < 8; nt++) {
                const int n = bn + wn + nt * 8 + lc4 * 2;
                float v0 = acc[mt][nt][half * 2 + 0] + bias[n];
                float v1 = acc[mt][nt][half * 2 + 1] + bias[n + 1];
                if (MODE == 1) {
                    const int b = m >> 11, t = m & (SEQ - 1);
                    const int head = n >> 6, d = n & (DH - 1);
                    const size_t off = (size_t)((b * NH + head) * SEQ + t) * DH + d;
                    uint32_t h, l;
                    split2(v0, v1, h, l);
                    *(uint32_t*)(Chi + off) = h;
                    *(uint32_t*)(Clo + off) = l;
                } else if (MODE == 2) {
                    v0 = 0.5f * v0 * (1.f + erff(v0 * 0.70710678118654752f));
                    v1 = 0.5f * v1 * (1.f + erff(v1 * 0.70710678118654752f));
                    const size_t off = (size_t)m * N + n;
                    uint32_t h, l;
                    split2(v0, v1, h, l);
                    *(uint32_t*)(Chi + off) = h;
                    *(uint32_t*)(Clo + off) = l;
                } else if (MODE == 3) {
                    float2 rv = *(const float2*)(res + (size_t)m * N + n);
                    float2 v; v.x = v0 + rv.x; v.y = v1 + rv.y;
                    *(float2*)(Cf + (size_t)m * N + n) = v;
                } else {
                    const float gv = gate[m >> 11];
                    float2 xv  = *(const float2*)(res  + (size_t)m * N + n);
                    float2 x1v = *(const float2*)(res2 + (size_t)m * N + n);
                    float2 v;
                    v.x = xv.x + gv * (x1v.x + v0 - xv.x);
                    v.y = xv.y + gv * (x1v.y + v1 - xv.y);
                    *(float2*)(Cf + (size_t)m * N + n) = v;
                }
            }
        }
    }
}

// ============ Tensor-core causal flash attention (pre-split bf16 inputs) ============
#define AK_HI 0
#define AK_LO 9216
#define AV_HI 18432
#define AV_LO 27648

__global__ void __launch_bounds__(256) attn_mma(
    const __nv_bfloat16* __restrict__ qhi, const __nv_bfloat16* __restrict__ qlo,
    const __nv_bfloat16* __restrict__ khi, const __nv_bfloat16* __restrict__ klo,
    const __nv_bfloat16* __restrict__ vhi, const __nv_bfloat16* __restrict__ vlo,
    __nv_bfloat16* __restrict__ ctxh, __nv_bfloat16* __restrict__ ctxl)
{
    __shared__ __align__(16) char smem[36864];
    const uint32_t sb = smem_u32(smem);
    const int qt = blockIdx.x;
    const int bh = blockIdx.y;
    const int b = bh >> 4, h = bh & (NH - 1);
    const int tid = threadIdx.x;
    const int lane = tid & 31, wid = tid >> 5;
    const int lr4 = lane >> 2, lc4 = lane & 3;
    const int rw = qt * 128 + wid * 16;

    const size_t base = (size_t)bh * SEQ * DH;
    const __nv_bfloat16* Qh = qhi + base;
    const __nv_bfloat16* Ql = qlo + base;
    const __nv_bfloat16* Kh = khi + base;
    const __nv_bfloat16* Kl = klo + base;
    const __nv_bfloat16* Vh = vhi + base;
    const __nv_bfloat16* Vl = vlo + base;

    // ---- Q fragments directly from pre-split planes ----
    uint32_t qfh[4][4], qfl[4][4];
    #pragma unroll
    for (int ks = 0; ks < 4; ks++) {
        #pragma unroll
        for (int j = 0; j < 4; j++) {
            const int row = rw + lr4 + (j & 1) * 8;
            const int d   = ks * 16 + lc4 * 2 + (j >> 1) * 8;
            qfh[ks][j] = *(const uint32_t*)(Qh + (size_t)row * DH + d);
            qfl[ks][j] = *(const uint32_t*)(Ql + (size_t)row * DH + d);
        }
    }

    float o[8][4];
    #pragma unroll
    for (int i = 0; i < 8; i++)
        #pragma unroll
        for (int j = 0; j < 4; j++) o[i][j] = 0.f;
    float m0 = -INFINITY, m1 = -INFINITY, l0 = 0.f, l1 = 0.f;

    const int nt_row = (lane & 7) + ((lane >> 4) & 1) * 8;
    const int nt_col = ((lane >> 3) & 1) * 8;
    const int tr_row = (lane & 7) + ((lane >> 3) & 1) * 8;
    const int tr_col = (lane >> 4) * 8;

    const int nkt = 2 * qt + 2;
    for (int kt = 0; kt < nkt; kt++) {
        const int kbase = kt * 64;
        __syncthreads();
        // ---- copy K/V hi/lo tiles (bf16, no conversion): 64 rows x 128B each ----
        #pragma unroll
        for (int i = 0; i < 2; i++) {
            const int idx = i * 256 + tid;
            const int kv = idx >> 3, c = idx & 7;
            const size_t go = (size_t)(kbase + kv) * DH * 2 + c * 16;
            const uint32_t so = (uint32_t)(kv * 144 + c * 16);
            *(uint4*)(smem + AK_HI + so) = *(const uint4*)((const char*)Kh + go);
            *(uint4*)(smem + AK_LO + so) = *(const uint4*)((const char*)Kl + go);
            *(uint4*)(smem + AV_HI + so) = *(const uint4*)((const char*)Vh + go);
            *(uint4*)(smem + AV_LO + so) = *(const uint4*)((const char*)Vl + go);
        }
        __syncthreads();

        if (kbase >= rw + 16) continue;

        // ---- S = Q K^T (3-term split) ----
        float s[8][4];
        #pragma unroll
        for (int i = 0; i < 8; i++)
            #pragma unroll
            for (int j = 0; j < 4; j++) s[i][j] = 0.f;
        #pragma unroll
        for (int ks = 0; ks < 4; ks++) {
            #pragma unroll
            for (int nb2 = 0; nb2 < 4; nb2++) {
                const uint32_t kaddr = sb + AK_HI
                    + (uint32_t)((nb2 * 16 + nt_row) * 144 + (ks * 16 + nt_col) * 2);
                uint32_t kh[4], kl[4];
                ldmatrix_x4(kh, kaddr);
                ldmatrix_x4(kl, kaddr + (AK_LO - AK_HI));
                mma_bf16(s[nb2*2],   qfh[ks], kh[0], kh[1]);
                mma_bf16(s[nb2*2+1], qfh[ks], kh[2], kh[3]);
                mma_bf16(s[nb2*2],   qfh[ks], kl[0], kl[1]);
                mma_bf16(s[nb2*2+1], qfh[ks], kl[2], kl[3]);
                mma_bf16(s[nb2*2],   qfl[ks], kh[0], kh[1]);
                mma_bf16(s[nb2*2+1], qfl[ks], kh[2], kh[3]);
            }
        }
        // ---- scale (1/sqrt(64)) + causal mask ----
        #pragma unroll
        for (int nb = 0; nb < 8; nb++)
            #pragma unroll
            for (int j = 0; j < 4; j++) s[nb][j] *= 0.125f;
        if (kbase + 63 > rw) {
            #pragma unroll
            for (int nb = 0; nb < 8; nb++)
                #pragma unroll
                for (int j = 0; j < 4; j++) {
                    const int qrow = rw + lr4 + (j >> 1) * 8;
                    const int kv = kbase + nb * 8 + lc4 * 2 + (j & 1);
                    if (kv > qrow) s[nb][j] = -INFINITY;
                }
        }
        // ---- online softmax ----
        float mx0 = -INFINITY, mx1 = -INFINITY;
        #pragma unroll
        for (int nb = 0; nb < 8; nb++) {
            mx0 = fmaxf(mx0, fmaxf(s[nb][0], s[nb][1]));
            mx1 = fmaxf(mx1, fmaxf(s[nb][2], s[nb][3]));
        }
        #pragma unroll
        for (int off = 1; off <= 2; off <<= 1) {
            mx0 = fmaxf(mx0, __shfl_xor_sync(0xffffffffu, mx0, off));
            mx1 = fmaxf(mx1, __shfl_xor_sync(0xffffffffu, mx1, off));
        }
        const float mn0 = fmaxf(m0, mx0), mn1 = fmaxf(m1, mx1);
        const float c0 = __expf(m0 - mn0), c1 = __expf(m1 - mn1);
        m0 = mn0; m1 = mn1;
        float rs0 = 0.f, rs1 = 0.f;
        #pragma unroll
        for (int nb = 0; nb < 8; nb++) {
            s[nb][0] = __expf(s[nb][0] - mn0);
            s[nb][1] = __expf(s[nb][1] - mn0);
            s[nb][2] = __expf(s[nb][2] - mn1);
            s[nb][3] = __expf(s[nb][3] - mn1);
            rs0 += s[nb][0] + s[nb][1];
            rs1 += s[nb][2] + s[nb][3];
        }
        #pragma unroll
        for (int off = 1; off <= 2; off <<= 1) {
            rs0 += __shfl_xor_sync(0xffffffffu, rs0, off);
            rs1 += __shfl_xor_sync(0xffffffffu, rs1, off);
        }
        l0 = l0 * c0 + rs0;
        l1 = l1 * c1 + rs1;
        #pragma unroll
        for (int nb = 0; nb < 8; nb++) {
            o[nb][0] *= c0; o[nb][1] *= c0;
            o[nb][2] *= c1; o[nb][3] *= c1;
        }
        // ---- pack P bf16 ----
        uint32_t pa[4][4];
        #pragma unroll
        for (int ks = 0; ks < 4; ks++) {
            pa[ks][0] = bf2_u32(__float22bfloat162_rn(make_float2(s[2*ks][0],   s[2*ks][1])));
            pa[ks][1] = bf2_u32(__float22bfloat162_rn(make_float2(s[2*ks][2],   s[2*ks][3])));
            pa[ks][2] = bf2_u32(__float22bfloat162_rn(make_float2(s[2*ks+1][0], s[2*ks+1][1])));
            pa[ks][3] = bf2_u32(__float22bfloat162_rn(make_float2(s[2*ks+1][2], s[2*ks+1][3])));
        }
        // ---- O += P V (V split 2-term) ----
        #pragma unroll
        for (int ks = 0; ks < 4; ks++) {
            #pragma unroll
            for (int db2 = 0; db2 < 4; db2++) {
                const uint32_t vaddr = sb + AV_HI
                    + (uint32_t)((ks * 16 + tr_row) * 144 + (db2 * 16 + tr_col) * 2);
                uint32_t vh[4], vl[4];
                ldmatrix_x4t(vh, vaddr);
                ldmatrix_x4t(vl, vaddr + (AV_LO - AV_HI));
                mma_bf16(o[db2*2],   pa[ks], vh[0], vh[1]);
                mma_bf16(o[db2*2+1], pa[ks], vh[2], vh[3]);
                mma_bf16(o[db2*2],   pa[ks], vl[0], vl[1]);
                mma_bf16(o[db2*2+1], pa[ks], vl[2], vl[3]);
            }
        }
    }

    // ---- finalize + store ctx as hi/lo bf16 [B,T,DM] ----
    const float i0 = 1.f / l0, i1 = 1.f / l1;
    #pragma unroll
    for (int nb = 0; nb < 8; nb++) {
        const int d = h * DH + nb * 8 + lc4 * 2;
        {
            const int row = rw + lr4;
            const size_t off = (size_t)(b * SEQ + row) * DM + d;
            uint32_t hh, ll;
            split2(o[nb][0] * i0, o[nb][1] * i0, hh, ll);
            *(uint32_t*)(ctxh + off) = hh;
            *(uint32_t*)(ctxl + off) = ll;
        }
        {
            const int row = rw + lr4 + 8;
            const size_t off = (size_t)(b * SEQ + row) * DM + d;
            uint32_t hh, ll;
            split2(o[nb][2] * i1, o[nb][3] * i1, hh, ll);
            *(uint32_t*)(ctxh + off) = hh;
            *(uint32_t*)(ctxl + off) = ll;
        }
    }
}

// ---------------- launch ----------------
extern "C" void kernel_launch(void* const* d_in, const int* in_sizes, int n_in,
                              void* d_out, int out_size)
{
    const float* x      = (const float*)d_in[0];
    const float* gate   = (const float*)d_in[1];
    const float* Wq     = (const float*)d_in[2];
    const float* bq     = (const float*)d_in[3];
    const float* Wk     = (const float*)d_in[4];
    const float* bk     = (const float*)d_in[5];
    const float* Wv     = (const float*)d_in[6];
    const float* bv     = (const float*)d_in[7];
    const float* Wo     = (const float*)d_in[8];
    const float* bo     = (const float*)d_in[9];
    const float* W1     = (const float*)d_in[10];
    const float* b1     = (const float*)d_in[11];
    const float* W2     = (const float*)d_in[12];
    const float* b2     = (const float*)d_in[13];
    const float* gamma1 = (const float*)d_in[14];
    const float* beta1  = (const float*)d_in[15];
    const float* gamma2 = (const float*)d_in[16];
    const float* beta2  = (const float*)d_in[17];
    float* out = (float*)d_out;

    __nv_bfloat16 *hh, *hl, *qh, *ql, *kh, *kl, *vh, *vl, *ch, *cl, *fh, *fl;
    __nv_bfloat16 *wqh, *wql, *wkh, *wkl, *wvh, *wvl, *woh, *wol, *w1h, *w1l, *w2h, *w2l;
    float *x1;
    cudaGetSymbolAddress((void**)&hh, g_hh);   cudaGetSymbolAddress((void**)&hl, g_hl);
    cudaGetSymbolAddress((void**)&qh, g_qhi);  cudaGetSymbolAddress((void**)&ql, g_qlo);
    cudaGetSymbolAddress((void**)&kh, g_khi);  cudaGetSymbolAddress((void**)&kl, g_klo);
    cudaGetSymbolAddress((void**)&vh, g_vhi);  cudaGetSymbolAddress((void**)&vl, g_vlo);
    cudaGetSymbolAddress((void**)&ch, g_chi);  cudaGetSymbolAddress((void**)&cl, g_clo);
    cudaGetSymbolAddress((void**)&fh, g_fhi);  cudaGetSymbolAddress((void**)&fl, g_flo);
    cudaGetSymbolAddress((void**)&x1, g_x1);
    cudaGetSymbolAddress((void**)&wqh, g_wqh); cudaGetSymbolAddress((void**)&wql, g_wql);
    cudaGetSymbolAddress((void**)&wkh, g_wkh); cudaGetSymbolAddress((void**)&wkl, g_wkl);
    cudaGetSymbolAddress((void**)&wvh, g_wvh); cudaGetSymbolAddress((void**)&wvl, g_wvl);
    cudaGetSymbolAddress((void**)&woh, g_woh); cudaGetSymbolAddress((void**)&wol, g_wol);
    cudaGetSymbolAddress((void**)&w1h, g_w1h); cudaGetSymbolAddress((void**)&w1l, g_w1l);
    cudaGetSymbolAddress((void**)&w2h, g_w2h); cudaGetSymbolAddress((void**)&w2l, g_w2l);

    cudaFuncSetAttribute(mma_gemm<1>, cudaFuncAttributeMaxDynamicSharedMemorySize, SMEM_BYTES);
    cudaFuncSetAttribute(mma_gemm<2>, cudaFuncAttributeMaxDynamicSharedMemorySize, SMEM_BYTES);
    cudaFuncSetAttribute(mma_gemm<3>, cudaFuncAttributeMaxDynamicSharedMemorySize, SMEM_BYTES);
    cudaFuncSetAttribute(mma_gemm<4>, cudaFuncAttributeMaxDynamicSharedMemorySize, SMEM_BYTES);

    // 0. split weights to hi/lo bf16 (once per launch, deterministic)
    const int n4a = DM*DM/4, n4b = DM*DFF/4;
    split_k<<<(n4a+255)/256, 256>>>((const float4*)Wq, (uint2*)wqh, (uint2*)wql, n4a);
    split_k<<<(n4a+255)/256, 256>>>((const float4*)Wk, (uint2*)wkh, (uint2*)wkl, n4a);
    split_k<<<(n4a+255)/256, 256>>>((const float4*)Wv, (uint2*)wvh, (uint2*)wvl, n4a);
    split_k<<<(n4a+255)/256, 256>>>((const float4*)Wo, (uint2*)woh, (uint2*)wol, n4a);
    split_k<<<(n4b+255)/256, 256>>>((const float4*)W1, (uint2*)w1h, (uint2*)w1l, n4b);
    split_k<<<(n4b+255)/256, 256>>>((const float4*)W2, (uint2*)w2h, (uint2*)w2l, n4b);

    // 1. h = LN(x) -> hi/lo
    ln_kernel<<<MROWS, 256>>>(x, gamma1, beta1, hh, hl);

    // 2. QKV projections -> hi/lo bf16 [B,H,T,D]
    dim3 g1(DM/128, MROWS/128);
    mma_gemm<1><<<g1, 256, SMEM_BYTES>>>(hh, hl, wqh, wql, bq, nullptr, qh, ql,
                                         MROWS, DM, DM, nullptr, nullptr, nullptr);
    mma_gemm<1><<<g1, 256, SMEM_BYTES>>>(hh, hl, wkh, wkl, bk, nullptr, kh, kl,
                                         MROWS, DM, DM, nullptr, nullptr, nullptr);
    mma_gemm<1><<<g1, 256, SMEM_BYTES>>>(hh, hl, wvh, wvl, bv, nullptr, vh, vl,
                                         MROWS, DM, DM, nullptr, nullptr, nullptr);

    // 3. causal attention -> ctx hi/lo
    attn_mma<<<dim3(SEQ/128, BATCH*NH), 256>>>(qh, ql, kh, kl, vh, vl, ch, cl);

    // 4. x1 = ctx@Wo + bo + x (fp32)
    mma_gemm<3><<<g1, 256, SMEM_BYTES>>>(ch, cl, woh, wol, bo, x1, nullptr, nullptr,
                                         MROWS, DM, DM, x, nullptr, nullptr);

    // 5. h = LN(x1) -> hi/lo
    ln_kernel<<<MROWS, 256>>>(x1, gamma2, beta2, hh, hl);

    // 6. ff = GELU(h@W1 + b1) -> hi/lo
    mma_gemm<2><<<dim3(DFF/128, MROWS/128), 256, SMEM_BYTES>>>(
        hh, hl, w1h, w1l, b1, nullptr, fh, fl, MROWS, DFF, DM, nullptr, nullptr, nullptr);

    // 7. out = x + g*(x1 + (ff@W2 + b2) - x) (fp32)
    mma_gemm<4><<<g1, 256, SMEM_BYTES>>>(fh, fl, w2h, w2l, b2, out, nullptr, nullptr,
                                         MROWS, DM, DFF, x, x1, gate);
}